// round 1
// baseline (speedup 1.0000x reference)
#include <cuda_runtime.h>

#define HH 512
#define WW 512
#define NIMG 12          // b*c = 4*3
#define RAD 3
#define ITERS 6
#define TX 64
#define TY 32
#define TILE_W (TX + 2*RAD)   // 70
#define TILE_H (TY + 2*RAD)   // 38
#define SV_H   (TY + RAD)     // 35
#define SPITCH (TX + 8)       // 72, padded shared pitch

// ping-pong scratch (allocation-free: static device globals)
__device__ float g_imA[NIMG*HH*WW];
__device__ float g_ptA[NIMG*HH*WW];
__device__ float g_imB[NIMG*HH*WW];
__device__ float g_ptB[NIMG*HH*WW];

__global__ __launch_bounds__(256)
void swf_step(const float* __restrict__ im_in, const float* __restrict__ pt_in,
              float* __restrict__ im_out, float* __restrict__ pt_out,
              int write_im)
{
    __shared__ float s_im[TILE_H][SPITCH];
    __shared__ float s_pt[TILE_H][SPITCH];
    __shared__ float sv_im[SV_H][SPITCH];   // vertical 4-row sums
    __shared__ float sv_pt[SV_H][SPITCH];

    const int img = blockIdx.z;
    const int x0 = blockIdx.x * TX;
    const int y0 = blockIdx.y * TY;
    const float* imI = im_in + (size_t)img * HH * WW;
    const float* ptI = pt_in + (size_t)img * HH * WW;

    const int tid = threadIdx.y * 64 + threadIdx.x;

    // ---- load tiles with halo (zero pad outside image) ----
    for (int idx = tid; idx < TILE_H * TILE_W; idx += 256) {
        int ly = idx / TILE_W, lx = idx - ly * TILE_W;
        int gy = y0 - RAD + ly, gx = x0 - RAD + lx;
        bool inb = (gy >= 0) && (gy < HH) && (gx >= 0) && (gx < WW);
        float a = 0.f, b = 0.f;
        if (inb) {
            int g = gy * WW + gx;
            a = imI[g];
            b = ptI[g];
        }
        s_im[ly][lx] = a;
        s_pt[ly][lx] = b;
    }
    __syncthreads();

    // ---- vertical 4-row partial sums: SV[j] = s[j]+s[j+1]+s[j+2]+s[j+3] ----
    for (int idx = tid; idx < SV_H * TILE_W; idx += 256) {
        int j = idx / TILE_W, lx = idx - j * TILE_W;
        sv_im[j][lx] = (s_im[j][lx] + s_im[j+1][lx]) + (s_im[j+2][lx] + s_im[j+3][lx]);
        sv_pt[j][lx] = (s_pt[j][lx] + s_pt[j+1][lx]) + (s_pt[j+2][lx] + s_pt[j+3][lx]);
    }
    __syncthreads();

    const float inv16 = 1.f / 16.f;
    const float inv28 = 1.f / 28.f;
    const int ox = threadIdx.x;

    for (int oy = threadIdx.y; oy < TY; oy += 4) {
        // ---- im means ----
        float u0 = sv_im[oy][ox],   u1 = sv_im[oy][ox+1], u2 = sv_im[oy][ox+2],
              u3 = sv_im[oy][ox+3], u4 = sv_im[oy][ox+4], u5 = sv_im[oy][ox+5],
              u6 = sv_im[oy][ox+6];
        float v0 = sv_im[oy+3][ox],   v1 = sv_im[oy+3][ox+1], v2 = sv_im[oy+3][ox+2],
              v3 = sv_im[oy+3][ox+3], v4 = sv_im[oy+3][ox+4], v5 = sv_im[oy+3][ox+5],
              v6 = sv_im[oy+3][ox+6];
        float c0 = s_im[oy+3][ox],   c1 = s_im[oy+3][ox+1], c2 = s_im[oy+3][ox+2],
              c3 = s_im[oy+3][ox+3], c4 = s_im[oy+3][ox+4], c5 = s_im[oy+3][ox+5],
              c6 = s_im[oy+3][ox+6];

        float qnw = (u0 + u1) + (u2 + u3);
        float qne = (u3 + u4) + (u5 + u6);
        float qsw = (v0 + v1) + (v2 + v3);
        float qse = (v3 + v4) + (v5 + v6);
        float hl  = (c0 + c1) + (c2 + c3);
        float hr  = (c3 + c4) + (c5 + c6);
        float zc  = c3;

        float di[8];
        di[0] = ((qnw + qsw) - hl) * inv28;   // L
        di[1] = ((qne + qse) - hr) * inv28;   // R
        di[2] = ((qnw + qne) - u3) * inv28;   // U
        di[3] = ((qsw + qse) - v3) * inv28;   // D
        di[4] = qnw * inv16;                  // NW
        di[5] = qne * inv16;                  // NE
        di[6] = qsw * inv16;                  // SW
        di[7] = qse * inv16;                  // SE

        // ---- pert means ----
        float pu0 = sv_pt[oy][ox],   pu1 = sv_pt[oy][ox+1], pu2 = sv_pt[oy][ox+2],
              pu3 = sv_pt[oy][ox+3], pu4 = sv_pt[oy][ox+4], pu5 = sv_pt[oy][ox+5],
              pu6 = sv_pt[oy][ox+6];
        float pv0 = sv_pt[oy+3][ox],   pv1 = sv_pt[oy+3][ox+1], pv2 = sv_pt[oy+3][ox+2],
              pv3 = sv_pt[oy+3][ox+3], pv4 = sv_pt[oy+3][ox+4], pv5 = sv_pt[oy+3][ox+5],
              pv6 = sv_pt[oy+3][ox+6];
        float pc0 = s_pt[oy+3][ox],   pc1 = s_pt[oy+3][ox+1], pc2 = s_pt[oy+3][ox+2],
              pc3 = s_pt[oy+3][ox+3], pc4 = s_pt[oy+3][ox+4], pc5 = s_pt[oy+3][ox+5],
              pc6 = s_pt[oy+3][ox+6];

        float pqnw = (pu0 + pu1) + (pu2 + pu3);
        float pqne = (pu3 + pu4) + (pu5 + pu6);
        float pqsw = (pv0 + pv1) + (pv2 + pv3);
        float pqse = (pv3 + pv4) + (pv5 + pv6);
        float phl  = (pc0 + pc1) + (pc2 + pc3);
        float phr  = (pc3 + pc4) + (pc5 + pc6);

        float dp[8];
        dp[0] = ((pqnw + pqsw) - phl) * inv28;
        dp[1] = ((pqne + pqse) - phr) * inv28;
        dp[2] = ((pqnw + pqne) - pu3) * inv28;
        dp[3] = ((pqsw + pqse) - pv3) * inv28;
        dp[4] = pqnw * inv16;
        dp[5] = pqne * inv16;
        dp[6] = pqsw * inv16;
        dp[7] = pqse * inv16;

        // ---- argmin over |mean_im - z| in reference order L,R,U,D,NW,NE,SW,SE ----
        float ba = fabsf(di[0] - zc);
        float bi = di[0];
        float bp = dp[0];
        #pragma unroll
        for (int k = 1; k < 8; k++) {
            float a = fabsf(di[k] - zc);
            bool t = a < ba;          // strict <: first min wins on ties (matches argmin)
            ba = t ? a : ba;
            bi = t ? di[k] : bi;
            bp = t ? dp[k] : bp;
        }

        int gidx = img * HH * WW + (y0 + oy) * WW + (x0 + ox);
        if (write_im) im_out[gidx] = bi;
        pt_out[gidx] = bp;
    }
}

extern "C" void kernel_launch(void* const* d_in, const int* in_sizes, int n_in,
                              void* d_out, int out_size)
{
    const float* im = (const float*)d_in[0];
    const float* pt = (const float*)d_in[1];
    float* out = (float*)d_out;

    float *imA, *ptA, *imB, *ptB;
    cudaGetSymbolAddress((void**)&imA, g_imA);
    cudaGetSymbolAddress((void**)&ptA, g_ptA);
    cudaGetSymbolAddress((void**)&imB, g_imB);
    cudaGetSymbolAddress((void**)&ptB, g_ptB);

    dim3 grid(WW / TX, HH / TY, NIMG);   // (8,16,12)
    dim3 block(64, 4);

    // 6 iterations, ping-pong; final iteration writes pert straight to d_out
    swf_step<<<grid, block>>>(im,  pt,  imA, ptA, 1);
    swf_step<<<grid, block>>>(imA, ptA, imB, ptB, 1);
    swf_step<<<grid, block>>>(imB, ptB, imA, ptA, 1);
    swf_step<<<grid, block>>>(imA, ptA, imB, ptB, 1);
    swf_step<<<grid, block>>>(imB, ptB, imA, ptA, 1);
    swf_step<<<grid, block>>>(imA, ptA, imB, out, 0);
}

// round 2
// speedup vs baseline: 1.5995x; 1.5995x over previous
#include <cuda_runtime.h>

#define HH 512
#define WW 512
#define NIMG 12
#define RAD 3
#define TX 64
#define TY 32
#define TILE_W 70            // TX + 2*RAD
#define TILE_H 38            // TY + 2*RAD
#define SV_H   35            // TY + RAD
#define PITCH  76            // padded, float4-aligned, decorrelates banks (76 mod 32 = 12)

// ping-pong scratch (allocation-free: static device globals)
__device__ float g_imA[NIMG*HH*WW];
__device__ float g_ptA[NIMG*HH*WW];
__device__ float g_imB[NIMG*HH*WW];
__device__ float g_ptB[NIMG*HH*WW];

__global__ __launch_bounds__(256)
void swf_step(const float* __restrict__ im_in, const float* __restrict__ pt_in,
              float* __restrict__ im_out, float* __restrict__ pt_out,
              int write_im)
{
    __shared__ float s [2][TILE_H][PITCH];
    __shared__ float sv[2][SV_H][PITCH];

    const int img = blockIdx.z;
    const int x0 = blockIdx.x * TX;
    const int y0 = blockIdx.y * TY;
    const float* __restrict__ imI = im_in + (size_t)img * HH * WW;
    const float* __restrict__ ptI = pt_in + (size_t)img * HH * WW;

    const int tid = threadIdx.x;

    // ---- stage 1: load both tiles with halo (72 cols so float4 reads stay in-init data) ----
    for (int idx = tid; idx < 2 * TILE_H * 72; idx += 256) {
        int a  = idx >= TILE_H * 72;
        int r  = idx - a * TILE_H * 72;
        int ly = r / 72, lx = r - ly * 72;
        int gy = y0 - RAD + ly, gx = x0 - RAD + lx;
        float val = 0.f;
        if (gy >= 0 && gy < HH && gx >= 0 && gx < WW)
            val = (a ? ptI : imI)[gy * WW + gx];
        s[a][ly][lx] = val;
    }
    __syncthreads();

    // ---- stage 2: vertical 4-row sums, float4-vectorized (18 groups cover cols 0..71) ----
    for (int idx = tid; idx < 2 * SV_H * 18; idx += 256) {
        int a = idx >= SV_H * 18;
        int r = idx - a * SV_H * 18;
        int j = r / 18, lx = (r - j * 18) * 4;
        float4 r0 = *(const float4*)&s[a][j    ][lx];
        float4 r1 = *(const float4*)&s[a][j + 1][lx];
        float4 r2 = *(const float4*)&s[a][j + 2][lx];
        float4 r3 = *(const float4*)&s[a][j + 3][lx];
        float4 o;
        o.x = (r0.x + r1.x) + (r2.x + r3.x);
        o.y = (r0.y + r1.y) + (r2.y + r3.y);
        o.z = (r0.z + r1.z) + (r2.z + r3.z);
        o.w = (r0.w + r1.w) + (r2.w + r3.w);
        *(float4*)&sv[a][j][lx] = o;
    }
    __syncthreads();

    // ---- stage 3: each thread owns 8 consecutive output pixels in one row ----
    const int oy = tid >> 3;            // 0..31
    const int xs = (tid & 7) << 3;      // 0,8,...,56
    const float inv16 = 1.f / 16.f;
    const float inv28 = 1.f / 28.f;

    float u[16], v[16], c[16];
    float qu[11], qv[11], hc[11];
    float pu2[14], pv2[14], pc2[14];

    // ===== pass A: im -> argmin index + filtered im =====
    #pragma unroll
    for (int q4 = 0; q4 < 4; q4++) {
        float4 tu = *(const float4*)&sv[0][oy    ][xs + 4 * q4];
        float4 tv = *(const float4*)&sv[0][oy + 3][xs + 4 * q4];
        float4 tc = *(const float4*)&s [0][oy + 3][xs + 4 * q4];
        u[4*q4] = tu.x; u[4*q4+1] = tu.y; u[4*q4+2] = tu.z; u[4*q4+3] = tu.w;
        v[4*q4] = tv.x; v[4*q4+1] = tv.y; v[4*q4+2] = tv.z; v[4*q4+3] = tv.w;
        c[4*q4] = tc.x; c[4*q4+1] = tc.y; c[4*q4+2] = tc.z; c[4*q4+3] = tc.w;
    }
    #pragma unroll
    for (int i = 0; i < 14; i++) {
        pu2[i] = u[i] + u[i+1];
        pv2[i] = v[i] + v[i+1];
        pc2[i] = c[i] + c[i+1];
    }
    #pragma unroll
    for (int i = 0; i < 11; i++) {
        qu[i] = pu2[i] + pu2[i+2];
        qv[i] = pv2[i] + pv2[i+2];
        hc[i] = pc2[i] + pc2[i+2];
    }

    float bi[8];
    unsigned pack = 0;
    #pragma unroll
    for (int p = 0; p < 8; p++) {
        float qnw = qu[p], qne = qu[p+3], qsw = qv[p], qse = qv[p+3];
        float z = c[p+3];
        float dd[8];
        dd[0] = ((qnw + qsw) - hc[p  ]) * inv28;  // L
        dd[1] = ((qne + qse) - hc[p+3]) * inv28;  // R
        dd[2] = ((qnw + qne) - u[p+3]) * inv28;   // U
        dd[3] = ((qsw + qse) - v[p+3]) * inv28;   // D
        dd[4] = qnw * inv16;                       // NW
        dd[5] = qne * inv16;                       // NE
        dd[6] = qsw * inv16;                       // SW
        dd[7] = qse * inv16;                       // SE
        float best = fabsf(dd[0] - z);
        float bv = dd[0];
        int bk = 0;
        #pragma unroll
        for (int k = 1; k < 8; k++) {
            float aa = fabsf(dd[k] - z);
            if (aa < best) { best = aa; bv = dd[k]; bk = k; }  // strict <: first min wins
        }
        bi[p] = bv;
        pack |= (unsigned)bk << (3 * p);
    }

    const int gbase = img * HH * WW + (y0 + oy) * WW + (x0 + xs);
    if (write_im) {
        *(float4*)&im_out[gbase    ] = make_float4(bi[0], bi[1], bi[2], bi[3]);
        *(float4*)&im_out[gbase + 4] = make_float4(bi[4], bi[5], bi[6], bi[7]);
    }

    // ===== pass B: pert, select by stored index =====
    #pragma unroll
    for (int q4 = 0; q4 < 4; q4++) {
        float4 tu = *(const float4*)&sv[1][oy    ][xs + 4 * q4];
        float4 tv = *(const float4*)&sv[1][oy + 3][xs + 4 * q4];
        float4 tc = *(const float4*)&s [1][oy + 3][xs + 4 * q4];
        u[4*q4] = tu.x; u[4*q4+1] = tu.y; u[4*q4+2] = tu.z; u[4*q4+3] = tu.w;
        v[4*q4] = tv.x; v[4*q4+1] = tv.y; v[4*q4+2] = tv.z; v[4*q4+3] = tv.w;
        c[4*q4] = tc.x; c[4*q4+1] = tc.y; c[4*q4+2] = tc.z; c[4*q4+3] = tc.w;
    }
    #pragma unroll
    for (int i = 0; i < 14; i++) {
        pu2[i] = u[i] + u[i+1];
        pv2[i] = v[i] + v[i+1];
        pc2[i] = c[i] + c[i+1];
    }
    #pragma unroll
    for (int i = 0; i < 11; i++) {
        qu[i] = pu2[i] + pu2[i+2];
        qv[i] = pv2[i] + pv2[i+2];
        hc[i] = pc2[i] + pc2[i+2];
    }

    float bp[8];
    #pragma unroll
    for (int p = 0; p < 8; p++) {
        float qnw = qu[p], qne = qu[p+3], qsw = qv[p], qse = qv[p+3];
        float dd[8];
        dd[0] = ((qnw + qsw) - hc[p  ]) * inv28;
        dd[1] = ((qne + qse) - hc[p+3]) * inv28;
        dd[2] = ((qnw + qne) - u[p+3]) * inv28;
        dd[3] = ((qsw + qse) - v[p+3]) * inv28;
        dd[4] = qnw * inv16;
        dd[5] = qne * inv16;
        dd[6] = qsw * inv16;
        dd[7] = qse * inv16;
        int bk = (pack >> (3 * p)) & 7;
        float bv = dd[0];
        #pragma unroll
        for (int k = 1; k < 8; k++) bv = (bk == k) ? dd[k] : bv;
        bp[p] = bv;
    }

    *(float4*)&pt_out[gbase    ] = make_float4(bp[0], bp[1], bp[2], bp[3]);
    *(float4*)&pt_out[gbase + 4] = make_float4(bp[4], bp[5], bp[6], bp[7]);
}

extern "C" void kernel_launch(void* const* d_in, const int* in_sizes, int n_in,
                              void* d_out, int out_size)
{
    const float* im = (const float*)d_in[0];
    const float* pt = (const float*)d_in[1];
    float* out = (float*)d_out;

    float *imA, *ptA, *imB, *ptB;
    cudaGetSymbolAddress((void**)&imA, g_imA);
    cudaGetSymbolAddress((void**)&ptA, g_ptA);
    cudaGetSymbolAddress((void**)&imB, g_imB);
    cudaGetSymbolAddress((void**)&ptB, g_ptB);

    dim3 grid(WW / TX, HH / TY, NIMG);   // (8,16,12) = 1536 blocks
    dim3 block(256);

    swf_step<<<grid, block>>>(im,  pt,  imA, ptA, 1);
    swf_step<<<grid, block>>>(imA, ptA, imB, ptB, 1);
    swf_step<<<grid, block>>>(imB, ptB, imA, ptA, 1);
    swf_step<<<grid, block>>>(imA, ptA, imB, ptB, 1);
    swf_step<<<grid, block>>>(imB, ptB, imA, ptA, 1);
    swf_step<<<grid, block>>>(imA, ptA, imB, out, 0);
}